// round 14
// baseline (speedup 1.0000x reference)
#include <cuda_runtime.h>

#define NN 50000
#define KD 128      // input dim of both layers (HID == IN_C == 128)
#define H1 128
#define H2 64
#define NE 800000
#define BM 64       // rows per GEMM tile
#define KC 32       // K chunk
#define NB 196      // ceil(NN/256)
#define NT ((NN + BM - 1) / BM)   // 782 row tiles
#define SPLIT_N 32768             // agg1/gemm2 overlap split (512 tiles)
#define SPLIT_T (SPLIT_N / BM)

// ---------------- scratch (device globals) ---------------------------------
__device__ float g_dinv[NN];
__device__ float4 g_hs1[(size_t)NN * H1 / 4];   // x@W1 (unscaled)
__device__ float4 g_x2[(size_t)NN * H1 / 4];    // relu output -> layer2 input
__device__ float4 g_hs2[(size_t)NN * H2 / 4];   // x2@W2 (unscaled)
__device__ int g_cnt[NN];
__device__ int g_rs[NN];                        // CSR segment starts (unordered)
__device__ int g_cur[NN];                       // fill cursors
__device__ int g_csr[NE];                       // src ids grouped by dst
__device__ int g_total;                         // segment allocator

typedef unsigned long long ull;

#define FMA2(c, a, b) \
    asm("fma.rn.f32x2 %0, %1, %2, %0;" : "+l"(c) : "l"(a), "l"(b))

__device__ __forceinline__ ull dup2(float a) {
    unsigned int u = __float_as_uint(a);
    ull r;
    asm("mov.b64 %0, {%1, %1};" : "=l"(r) : "r"(u));
    return r;
}

__device__ __forceinline__ void cpa16(float* d, const float* s) {
    unsigned sd_ = (unsigned)__cvta_generic_to_shared(d);
    asm volatile("cp.async.cg.shared.global [%0], [%1], 16;" :: "r"(sd_), "l"(s));
}
__device__ __forceinline__ void cpa16z(float* d) {
    unsigned sd_ = (unsigned)__cvta_generic_to_shared(d);
    asm volatile("cp.async.cg.shared.global [%0], [%1], 16, 0;"
                 :: "r"(sd_), "l"((const void*)g_dinv));
}

// ---------------- CSR build -------------------------------------------------
__global__ void k_zero_cnt() {
    int i = blockIdx.x * blockDim.x + threadIdx.x;
    if (i < NN) g_cnt[i] = 0;
    if (i == 0) g_total = 0;
}

__global__ void k_hist(const int* __restrict__ dst) {
    int t = blockIdx.x * blockDim.x + threadIdx.x;
    if (t >= NE / 4) return;
    int4 d4 = ((const int4*)dst)[t];
    atomicAdd(&g_cnt[d4.x], 1);
    atomicAdd(&g_cnt[d4.y], 1);
    atomicAdd(&g_cnt[d4.z], 1);
    atomicAdd(&g_cnt[d4.w], 1);
}

__global__ void k_alloc() {
    __shared__ int sd[256];
    __shared__ int base;
    int t = threadIdx.x;
    int i = blockIdx.x * 256 + t;
    int v = (i < NN) ? g_cnt[i] : 0;
    sd[t] = v;
    __syncthreads();
    for (int off = 1; off < 256; off <<= 1) {
        int x = (t >= off) ? sd[t - off] : 0;
        __syncthreads();
        sd[t] += x;
        __syncthreads();
    }
    if (t == 255) base = atomicAdd(&g_total, sd[255]);
    __syncthreads();
    if (i < NN) {
        int rs = base + sd[t] - v;
        g_rs[i]  = rs;
        g_cur[i] = rs;
        g_dinv[i] = rsqrtf((float)(v + 1));   // deg includes self loop
    }
}

__global__ void k_fill(const int* __restrict__ src, const int* __restrict__ dst) {
    int t = blockIdx.x * blockDim.x + threadIdx.x;
    if (t >= NE / 4) return;
    int4 s4 = ((const int4*)src)[t];
    int4 d4 = ((const int4*)dst)[t];
    g_csr[atomicAdd(&g_cur[d4.x], 1)] = s4.x;
    g_csr[atomicAdd(&g_cur[d4.y], 1)] = s4.y;
    g_csr[atomicAdd(&g_cur[d4.z], 1)] = s4.z;
    g_csr[atomicAdd(&g_cur[d4.w], 1)] = s4.w;
}

// ---------------- GEMM (cp.async double-buffered), BM=64 tiles --------------
// hs[i][j] = sum_k A[i][k] * W[k][j]
template <int NC>
__device__ __forceinline__ void gemm_body(const float* __restrict__ A,
                                          const float* __restrict__ W,
                                          float4* __restrict__ hs,
                                          int tile)
{
    constexpr int TN  = NC / 16;      // 8 / 4
    constexpr int TP  = TN / 2;       // 4 / 2
    constexpr int WS  = NC + 4;
    constexpr int AS  = KC + 4;
    constexpr int NCH = KD / KC;

    extern __shared__ float smem[];
    float* Wb0 = smem;                        // [2][KC][WS]
    float* Ab0 = smem + 2 * KC * WS;          // [2][BM][AS] row-major

    const int tid  = threadIdx.x;
    const int tx   = tid & 15, ty = tid >> 4;
    const int row0 = tile * BM;
    const int cb   = tx * TN;

    auto issue = [&](int c) {
        float* Wb = Wb0 + (c & 1) * KC * WS;
        float* Ab = Ab0 + (c & 1) * BM * AS;
        int k0 = c * KC;
        for (int i = tid; i < KC * (NC / 4); i += 256) {
            int kk = i / (NC / 4), c4 = i % (NC / 4);
            cpa16(Wb + kk * WS + c4 * 4, W + (size_t)(k0 + kk) * NC + c4 * 4);
        }
        for (int i = tid; i < BM * (KC / 4); i += 256) {
            int r = i >> 3, c4 = i & 7;       // KC/4 == 8
            int gr = row0 + r;
            float* d = Ab + r * AS + c4 * 4;
            if (gr < NN) cpa16(d, A + (size_t)gr * KD + k0 + c4 * 4);
            else         cpa16z(d);
        }
        asm volatile("cp.async.commit_group;");
    };

    ull accp[4][TP];
#pragma unroll
    for (int i = 0; i < 4; i++)
#pragma unroll
        for (int p = 0; p < TP; p++) accp[i][p] = 0ull;

    issue(0);
    for (int c = 0; c < NCH; c++) {
        if (c + 1 < NCH) {
            issue(c + 1);
            asm volatile("cp.async.wait_group 1;");
        } else {
            asm volatile("cp.async.wait_group 0;");
        }
        __syncthreads();

        const float* arow = Ab0 + (c & 1) * BM * AS + (ty * 4) * AS;
        const float* wrow = Wb0 + (c & 1) * KC * WS + cb;
#pragma unroll 8
        for (int kk = 0; kk < KC; kk++) {
            ull ap[4];
#pragma unroll
            for (int i = 0; i < 4; i++) ap[i] = dup2(arow[i * AS + kk]);

            ull bp[4];
            float4 b0 = *(const float4*)(wrow + (size_t)kk * WS);
            bp[0] = ((const ull*)&b0)[0]; bp[1] = ((const ull*)&b0)[1];
            if (TP == 4) {
                float4 b1 = *(const float4*)(wrow + (size_t)kk * WS + 4);
                bp[2] = ((const ull*)&b1)[0]; bp[3] = ((const ull*)&b1)[1];
            }
#pragma unroll
            for (int i = 0; i < 4; i++)
#pragma unroll
                for (int p = 0; p < TP; p++)
                    FMA2(accp[i][p], ap[i], bp[p]);
        }
        __syncthreads();
    }

#pragma unroll
    for (int i = 0; i < 4; i++) {
        int gr = row0 + ty * 4 + i;
        if (gr >= NN) continue;
        size_t base4 = ((size_t)gr * NC + cb) >> 2;
#pragma unroll
        for (int p2 = 0; p2 < TP / 2; p2++) {
            float2 lo = *(float2*)&accp[i][2 * p2];
            float2 hi = *(float2*)&accp[i][2 * p2 + 1];
            hs[base4 + p2] = make_float4(lo.x, lo.y, hi.x, hi.y);
        }
    }
}

__global__ void __launch_bounds__(256, 2) k_gemm1(const float* __restrict__ x,
                                                  const float* __restrict__ W1) {
    gemm_body<H1>(x, W1, g_hs1, blockIdx.x);
}
__global__ void __launch_bounds__(256, 2) k_gemm2(const float* __restrict__ W2,
                                                  int tile0) {
    gemm_body<H2>((const float*)g_x2, W2, g_hs2, tile0 + blockIdx.x);
}

// ---------------- CSR pull aggregation (dinv applied here) ------------------
__global__ void __launch_bounds__(256) k_agg1(const float* __restrict__ b1,
                                              int node0) {
    int w = node0 + blockIdx.x * 8 + (threadIdx.x >> 5);
    if (w >= NN) return;
    int lane = threadIdx.x & 31;

    float dd = g_dinv[w];
    float4 a = g_hs1[(size_t)w * 32 + lane];   // self loop
    a.x *= dd; a.y *= dd; a.z *= dd; a.w *= dd;

    int i   = g_rs[w];
    int end = i + g_cnt[w];
    for (; i + 4 <= end; i += 4) {
        int s0 = g_csr[i], s1 = g_csr[i + 1], s2 = g_csr[i + 2], s3 = g_csr[i + 3];
        float d0 = g_dinv[s0], d1 = g_dinv[s1], d2 = g_dinv[s2], d3 = g_dinv[s3];
        float4 v0 = g_hs1[(size_t)s0 * 32 + lane];
        float4 v1 = g_hs1[(size_t)s1 * 32 + lane];
        float4 v2 = g_hs1[(size_t)s2 * 32 + lane];
        float4 v3 = g_hs1[(size_t)s3 * 32 + lane];
        a.x += v0.x * d0 + v1.x * d1 + v2.x * d2 + v3.x * d3;
        a.y += v0.y * d0 + v1.y * d1 + v2.y * d2 + v3.y * d3;
        a.z += v0.z * d0 + v1.z * d1 + v2.z * d2 + v3.z * d3;
        a.w += v0.w * d0 + v1.w * d1 + v2.w * d2 + v3.w * d3;
    }
    for (; i < end; i++) {
        int s = g_csr[i];
        float ds = g_dinv[s];
        float4 v = g_hs1[(size_t)s * 32 + lane];
        a.x += v.x * ds; a.y += v.y * ds; a.z += v.z * ds; a.w += v.w * ds;
    }
    float4 b = *(const float4*)(b1 + lane * 4);
    a.x = fmaxf(fmaf(a.x, dd, b.x), 0.f);
    a.y = fmaxf(fmaf(a.y, dd, b.y), 0.f);
    a.z = fmaxf(fmaf(a.z, dd, b.z), 0.f);
    a.w = fmaxf(fmaf(a.w, dd, b.w), 0.f);
    g_x2[(size_t)w * 32 + lane] = a;
}

__global__ void __launch_bounds__(256) k_agg2(const float* __restrict__ b2,
                                              float* __restrict__ out) {
    int g = blockIdx.x * 16 + (threadIdx.x >> 4);
    if (g >= NN) return;
    int l = threadIdx.x & 15;

    float dd = g_dinv[g];
    float4 a = g_hs2[(size_t)g * 16 + l];      // self loop
    a.x *= dd; a.y *= dd; a.z *= dd; a.w *= dd;

    int i   = g_rs[g];
    int end = i + g_cnt[g];
    for (; i + 4 <= end; i += 4) {
        int s0 = g_csr[i], s1 = g_csr[i + 1], s2 = g_csr[i + 2], s3 = g_csr[i + 3];
        float d0 = g_dinv[s0], d1 = g_dinv[s1], d2 = g_dinv[s2], d3 = g_dinv[s3];
        float4 v0 = g_hs2[(size_t)s0 * 16 + l];
        float4 v1 = g_hs2[(size_t)s1 * 16 + l];
        float4 v2 = g_hs2[(size_t)s2 * 16 + l];
        float4 v3 = g_hs2[(size_t)s3 * 16 + l];
        a.x += v0.x * d0 + v1.x * d1 + v2.x * d2 + v3.x * d3;
        a.y += v0.y * d0 + v1.y * d1 + v2.y * d2 + v3.y * d3;
        a.z += v0.z * d0 + v1.z * d1 + v2.z * d2 + v3.z * d3;
        a.w += v0.w * d0 + v1.w * d1 + v2.w * d2 + v3.w * d3;
    }
    for (; i < end; i++) {
        int s = g_csr[i];
        float ds = g_dinv[s];
        float4 v = g_hs2[(size_t)s * 16 + l];
        a.x += v.x * ds; a.y += v.y * ds; a.z += v.z * ds; a.w += v.w * ds;
    }
    float4 b = *(const float4*)(b2 + l * 4);
    a.x = fmaf(a.x, dd, b.x);
    a.y = fmaf(a.y, dd, b.y);
    a.z = fmaf(a.z, dd, b.z);
    a.w = fmaf(a.w, dd, b.w);
    *(float4*)(out + (size_t)g * H2 + l * 4) = a;
}

// ---------------- launch ----------------------------------------------------
extern "C" void kernel_launch(void* const* d_in, const int* in_sizes, int n_in,
                              void* d_out, int out_size)
{
    const float* x  = (const float*)d_in[0];
    const int*   ei = (const int*)d_in[1];    // int32 (JAX default, x64 disabled)
    const float* W1 = (const float*)d_in[2];
    const float* b1 = (const float*)d_in[3];
    const float* W2 = (const float*)d_in[4];
    const float* b2 = (const float*)d_in[5];
    float* out = (float*)d_out;

    const int* src = ei;        // edge_index[0]
    const int* dst = ei + NE;   // edge_index[1]

    const int SMEM1 = (2 * KC * (H1 + 4) + 2 * BM * (KC + 4)) * (int)sizeof(float);
    const int SMEM2 = (2 * KC * (H2 + 4) + 2 * BM * (KC + 4)) * (int)sizeof(float);
    cudaFuncSetAttribute(k_gemm1, cudaFuncAttributeMaxDynamicSharedMemorySize, SMEM1);
    cudaFuncSetAttribute(k_gemm2, cudaFuncAttributeMaxDynamicSharedMemorySize, SMEM2);

    static cudaStream_t s_b = nullptr;
    static cudaEvent_t  ev_fork = nullptr, ev_join = nullptr, ev_lo = nullptr,
                        ev_g2lo = nullptr;
    if (s_b == nullptr) {
        cudaStreamCreateWithFlags(&s_b, cudaStreamNonBlocking);
        cudaEventCreateWithFlags(&ev_fork, cudaEventDisableTiming);
        cudaEventCreateWithFlags(&ev_join, cudaEventDisableTiming);
        cudaEventCreateWithFlags(&ev_lo,   cudaEventDisableTiming);
        cudaEventCreateWithFlags(&ev_g2lo, cudaEventDisableTiming);
    }

    // fork: CSR build concurrent with gemm1 (gemm no longer reads g_dinv)
    cudaEventRecord(ev_fork, (cudaStream_t)0);
    cudaStreamWaitEvent(s_b, ev_fork, 0);

    k_zero_cnt<<<(NN + 255) / 256, 256, 0, s_b>>>();
    k_hist<<<(NE / 4 + 255) / 256, 256, 0, s_b>>>(dst);
    k_alloc<<<NB, 256, 0, s_b>>>();
    k_fill<<<(NE / 4 + 255) / 256, 256, 0, s_b>>>(src, dst);
    cudaEventRecord(ev_join, s_b);

    k_gemm1<<<NT, 256, SMEM1>>>(x, W1);

    cudaStreamWaitEvent((cudaStream_t)0, ev_join, 0);

    // agg1_lo, then agg1_hi concurrent with gemm2_lo on side stream
    k_agg1<<<SPLIT_N / 8, 256>>>(b1, 0);
    cudaEventRecord(ev_lo, (cudaStream_t)0);
    cudaStreamWaitEvent(s_b, ev_lo, 0);
    k_gemm2<<<SPLIT_T, 256, SMEM2, s_b>>>(W2, 0);
    cudaEventRecord(ev_g2lo, s_b);

    k_agg1<<<(NN - SPLIT_N + 7) / 8, 256>>>(b1, SPLIT_N);

    cudaStreamWaitEvent((cudaStream_t)0, ev_g2lo, 0);
    k_gemm2<<<NT - SPLIT_T, 256, SMEM2>>>(W2, SPLIT_T);
    k_agg2<<<(NN + 15) / 16, 256>>>(b2, out);
}

// round 15
// speedup vs baseline: 1.1388x; 1.1388x over previous
#include <cuda_runtime.h>

#define NN 50000
#define KD 128      // input dim of both layers (HID == IN_C == 128)
#define H1 128
#define H2 64
#define NE 800000
#define BM 128      // rows per GEMM tile
#define KC 32       // K chunk
#define NB 196      // ceil(NN/256)
#define NT ((NN + BM - 1) / BM)   // 391 row tiles
#define SPLIT_T 240               // gemm2/agg1 overlap split (tiles)
#define SPLIT_N (SPLIT_T * BM)    // 30720 nodes

// ---------------- scratch (device globals) ---------------------------------
__device__ float g_dinv[NN];
__device__ float4 g_hs1[(size_t)NN * H1 / 4];   // x@W1 (unscaled)
__device__ float4 g_x2[(size_t)NN * H1 / 4];    // relu output -> layer2 input
__device__ float4 g_hs2[(size_t)NN * H2 / 4];   // x2@W2 (unscaled)
__device__ int g_cnt[NN];
__device__ int g_rs[NN];                        // CSR segment starts (unordered)
__device__ int g_cur[NN];                       // fill cursors
__device__ int g_csr[NE];                       // src ids grouped by dst
__device__ int g_total;                         // segment allocator

typedef unsigned long long ull;

#define FMA2(c, a, b) \
    asm("fma.rn.f32x2 %0, %1, %2, %0;" : "+l"(c) : "l"(a), "l"(b))

__device__ __forceinline__ ull dup2(float a) {
    unsigned int u = __float_as_uint(a);
    ull r;
    asm("mov.b64 %0, {%1, %1};" : "=l"(r) : "r"(u));
    return r;
}

__device__ __forceinline__ void cpa16(float* d, const float* s) {
    unsigned sd_ = (unsigned)__cvta_generic_to_shared(d);
    asm volatile("cp.async.cg.shared.global [%0], [%1], 16;" :: "r"(sd_), "l"(s));
}
__device__ __forceinline__ void cpa16z(float* d) {
    unsigned sd_ = (unsigned)__cvta_generic_to_shared(d);
    asm volatile("cp.async.cg.shared.global [%0], [%1], 16, 0;"
                 :: "r"(sd_), "l"((const void*)g_dinv));
}

// ---------------- CSR build -------------------------------------------------
__global__ void k_zero_cnt() {
    int i = blockIdx.x * blockDim.x + threadIdx.x;
    if (i < NN) g_cnt[i] = 0;
    if (i == 0) g_total = 0;
}

__global__ void k_hist(const int* __restrict__ dst) {
    int t = blockIdx.x * blockDim.x + threadIdx.x;
    if (t >= NE / 4) return;
    int4 d4 = ((const int4*)dst)[t];
    atomicAdd(&g_cnt[d4.x], 1);
    atomicAdd(&g_cnt[d4.y], 1);
    atomicAdd(&g_cnt[d4.z], 1);
    atomicAdd(&g_cnt[d4.w], 1);
}

__global__ void k_alloc() {
    __shared__ int sd[256];
    __shared__ int base;
    int t = threadIdx.x;
    int i = blockIdx.x * 256 + t;
    int v = (i < NN) ? g_cnt[i] : 0;
    sd[t] = v;
    __syncthreads();
    for (int off = 1; off < 256; off <<= 1) {
        int x = (t >= off) ? sd[t - off] : 0;
        __syncthreads();
        sd[t] += x;
        __syncthreads();
    }
    if (t == 255) base = atomicAdd(&g_total, sd[255]);
    __syncthreads();
    if (i < NN) {
        int rs = base + sd[t] - v;
        g_rs[i]  = rs;
        g_cur[i] = rs;
        g_dinv[i] = rsqrtf((float)(v + 1));   // deg includes self loop
    }
}

__global__ void k_fill(const int* __restrict__ src, const int* __restrict__ dst) {
    int t = blockIdx.x * blockDim.x + threadIdx.x;
    if (t >= NE / 4) return;
    int4 s4 = ((const int4*)src)[t];
    int4 d4 = ((const int4*)dst)[t];
    g_csr[atomicAdd(&g_cur[d4.x], 1)] = s4.x;
    g_csr[atomicAdd(&g_cur[d4.y], 1)] = s4.y;
    g_csr[atomicAdd(&g_cur[d4.z], 1)] = s4.z;
    g_csr[atomicAdd(&g_cur[d4.w], 1)] = s4.w;
}

// ---------------- GEMM (cp.async double-buffered), BM=128 -------------------
// hs[i][j] = sum_k A[i][k] * W[k][j]
template <int NC>
__device__ __forceinline__ void gemm_body(const float* __restrict__ A,
                                          const float* __restrict__ W,
                                          float4* __restrict__ hs,
                                          int tile)
{
    constexpr int TN  = NC / 16;      // 8 / 4
    constexpr int TP  = TN / 2;       // 4 / 2
    constexpr int WS  = NC + 4;
    constexpr int AS  = KC + 4;
    constexpr int NCH = KD / KC;

    extern __shared__ float smem[];
    float* Wb0 = smem;                        // [2][KC][WS]
    float* Ab0 = smem + 2 * KC * WS;          // [2][BM][AS] row-major

    const int tid  = threadIdx.x;
    const int tx   = tid & 15, ty = tid >> 4;
    const int row0 = tile * BM;
    const int cb   = tx * TN;

    auto issue = [&](int c) {
        float* Wb = Wb0 + (c & 1) * KC * WS;
        float* Ab = Ab0 + (c & 1) * BM * AS;
        int k0 = c * KC;
        for (int i = tid; i < KC * (NC / 4); i += 256) {
            int kk = i / (NC / 4), c4 = i % (NC / 4);
            cpa16(Wb + kk * WS + c4 * 4, W + (size_t)(k0 + kk) * NC + c4 * 4);
        }
        for (int i = tid; i < BM * (KC / 4); i += 256) {
            int r = i >> 3, c4 = i & 7;       // KC/4 == 8
            int gr = row0 + r;
            float* d = Ab + r * AS + c4 * 4;
            if (gr < NN) cpa16(d, A + (size_t)gr * KD + k0 + c4 * 4);
            else         cpa16z(d);
        }
        asm volatile("cp.async.commit_group;");
    };

    ull accp[8][TP];
#pragma unroll
    for (int i = 0; i < 8; i++)
#pragma unroll
        for (int p = 0; p < TP; p++) accp[i][p] = 0ull;

    issue(0);
    for (int c = 0; c < NCH; c++) {
        if (c + 1 < NCH) {
            issue(c + 1);
            asm volatile("cp.async.wait_group 1;");
        } else {
            asm volatile("cp.async.wait_group 0;");
        }
        __syncthreads();

        const float* arow = Ab0 + (c & 1) * BM * AS + (ty * 8) * AS;
        const float* wrow = Wb0 + (c & 1) * KC * WS + cb;
#pragma unroll 8
        for (int kk = 0; kk < KC; kk++) {
            ull ap[8];
#pragma unroll
            for (int i = 0; i < 8; i++) ap[i] = dup2(arow[i * AS + kk]);

            ull bp[4];
            float4 b0 = *(const float4*)(wrow + (size_t)kk * WS);
            bp[0] = ((const ull*)&b0)[0]; bp[1] = ((const ull*)&b0)[1];
            if (TP == 4) {
                float4 b1 = *(const float4*)(wrow + (size_t)kk * WS + 4);
                bp[2] = ((const ull*)&b1)[0]; bp[3] = ((const ull*)&b1)[1];
            }
#pragma unroll
            for (int i = 0; i < 8; i++)
#pragma unroll
                for (int p = 0; p < TP; p++)
                    FMA2(accp[i][p], ap[i], bp[p]);
        }
        __syncthreads();
    }

#pragma unroll
    for (int i = 0; i < 8; i++) {
        int gr = row0 + ty * 8 + i;
        if (gr >= NN) continue;
        size_t base4 = ((size_t)gr * NC + cb) >> 2;
#pragma unroll
        for (int p2 = 0; p2 < TP / 2; p2++) {
            float2 lo = *(float2*)&accp[i][2 * p2];
            float2 hi = *(float2*)&accp[i][2 * p2 + 1];
            hs[base4 + p2] = make_float4(lo.x, lo.y, hi.x, hi.y);
        }
    }
}

__global__ void __launch_bounds__(256, 2) k_gemm1(const float* __restrict__ x,
                                                  const float* __restrict__ W1) {
    gemm_body<H1>(x, W1, g_hs1, blockIdx.x);
}
__global__ void __launch_bounds__(256, 2) k_gemm2(const float* __restrict__ W2,
                                                  int tile0) {
    gemm_body<H2>((const float*)g_x2, W2, g_hs2, tile0 + blockIdx.x);
}

// ---------------- CSR pull aggregation (dinv applied here) ------------------
__global__ void __launch_bounds__(256) k_agg1(const float* __restrict__ b1,
                                              int node0) {
    int w = node0 + blockIdx.x * 8 + (threadIdx.x >> 5);
    if (w >= NN) return;
    int lane = threadIdx.x & 31;

    float dd = g_dinv[w];
    float4 a = g_hs1[(size_t)w * 32 + lane];   // self loop
    a.x *= dd; a.y *= dd; a.z *= dd; a.w *= dd;

    int i   = g_rs[w];
    int end = i + g_cnt[w];
    for (; i + 4 <= end; i += 4) {
        int s0 = g_csr[i], s1 = g_csr[i + 1], s2 = g_csr[i + 2], s3 = g_csr[i + 3];
        float d0 = g_dinv[s0], d1 = g_dinv[s1], d2 = g_dinv[s2], d3 = g_dinv[s3];
        float4 v0 = g_hs1[(size_t)s0 * 32 + lane];
        float4 v1 = g_hs1[(size_t)s1 * 32 + lane];
        float4 v2 = g_hs1[(size_t)s2 * 32 + lane];
        float4 v3 = g_hs1[(size_t)s3 * 32 + lane];
        a.x += v0.x * d0 + v1.x * d1 + v2.x * d2 + v3.x * d3;
        a.y += v0.y * d0 + v1.y * d1 + v2.y * d2 + v3.y * d3;
        a.z += v0.z * d0 + v1.z * d1 + v2.z * d2 + v3.z * d3;
        a.w += v0.w * d0 + v1.w * d1 + v2.w * d2 + v3.w * d3;
    }
    for (; i < end; i++) {
        int s = g_csr[i];
        float ds = g_dinv[s];
        float4 v = g_hs1[(size_t)s * 32 + lane];
        a.x += v.x * ds; a.y += v.y * ds; a.z += v.z * ds; a.w += v.w * ds;
    }
    float4 b = *(const float4*)(b1 + lane * 4);
    a.x = fmaxf(fmaf(a.x, dd, b.x), 0.f);
    a.y = fmaxf(fmaf(a.y, dd, b.y), 0.f);
    a.z = fmaxf(fmaf(a.z, dd, b.z), 0.f);
    a.w = fmaxf(fmaf(a.w, dd, b.w), 0.f);
    g_x2[(size_t)w * 32 + lane] = a;
}

__global__ void __launch_bounds__(256) k_agg2(const float* __restrict__ b2,
                                              float* __restrict__ out) {
    int g = blockIdx.x * 16 + (threadIdx.x >> 4);
    if (g >= NN) return;
    int l = threadIdx.x & 15;

    float dd = g_dinv[g];
    float4 a = g_hs2[(size_t)g * 16 + l];      // self loop
    a.x *= dd; a.y *= dd; a.z *= dd; a.w *= dd;

    int i   = g_rs[g];
    int end = i + g_cnt[g];
    for (; i + 4 <= end; i += 4) {
        int s0 = g_csr[i], s1 = g_csr[i + 1], s2 = g_csr[i + 2], s3 = g_csr[i + 3];
        float d0 = g_dinv[s0], d1 = g_dinv[s1], d2 = g_dinv[s2], d3 = g_dinv[s3];
        float4 v0 = g_hs2[(size_t)s0 * 16 + l];
        float4 v1 = g_hs2[(size_t)s1 * 16 + l];
        float4 v2 = g_hs2[(size_t)s2 * 16 + l];
        float4 v3 = g_hs2[(size_t)s3 * 16 + l];
        a.x += v0.x * d0 + v1.x * d1 + v2.x * d2 + v3.x * d3;
        a.y += v0.y * d0 + v1.y * d1 + v2.y * d2 + v3.y * d3;
        a.z += v0.z * d0 + v1.z * d1 + v2.z * d2 + v3.z * d3;
        a.w += v0.w * d0 + v1.w * d1 + v2.w * d2 + v3.w * d3;
    }
    for (; i < end; i++) {
        int s = g_csr[i];
        float ds = g_dinv[s];
        float4 v = g_hs2[(size_t)s * 16 + l];
        a.x += v.x * ds; a.y += v.y * ds; a.z += v.z * ds; a.w += v.w * ds;
    }
    float4 b = *(const float4*)(b2 + l * 4);
    a.x = fmaf(a.x, dd, b.x);
    a.y = fmaf(a.y, dd, b.y);
    a.z = fmaf(a.z, dd, b.z);
    a.w = fmaf(a.w, dd, b.w);
    *(float4*)(out + (size_t)g * H2 + l * 4) = a;
}

// ---------------- launch ----------------------------------------------------
extern "C" void kernel_launch(void* const* d_in, const int* in_sizes, int n_in,
                              void* d_out, int out_size)
{
    const float* x  = (const float*)d_in[0];
    const int*   ei = (const int*)d_in[1];    // int32 (JAX default, x64 disabled)
    const float* W1 = (const float*)d_in[2];
    const float* b1 = (const float*)d_in[3];
    const float* W2 = (const float*)d_in[4];
    const float* b2 = (const float*)d_in[5];
    float* out = (float*)d_out;

    const int* src = ei;        // edge_index[0]
    const int* dst = ei + NE;   // edge_index[1]

    const int SMEM1 = (2 * KC * (H1 + 4) + 2 * BM * (KC + 4)) * (int)sizeof(float);
    const int SMEM2 = (2 * KC * (H2 + 4) + 2 * BM * (KC + 4)) * (int)sizeof(float);
    cudaFuncSetAttribute(k_gemm1, cudaFuncAttributeMaxDynamicSharedMemorySize, SMEM1);
    cudaFuncSetAttribute(k_gemm2, cudaFuncAttributeMaxDynamicSharedMemorySize, SMEM2);

    static cudaStream_t s_b = nullptr;
    static cudaEvent_t  ev_fork = nullptr, ev_join = nullptr, ev_lo = nullptr,
                        ev_g2lo = nullptr;
    if (s_b == nullptr) {
        cudaStreamCreateWithFlags(&s_b, cudaStreamNonBlocking);
        cudaEventCreateWithFlags(&ev_fork, cudaEventDisableTiming);
        cudaEventCreateWithFlags(&ev_join, cudaEventDisableTiming);
        cudaEventCreateWithFlags(&ev_lo,   cudaEventDisableTiming);
        cudaEventCreateWithFlags(&ev_g2lo, cudaEventDisableTiming);
    }

    // fork: CSR build concurrent with gemm1 (gemm does not read g_dinv)
    cudaEventRecord(ev_fork, (cudaStream_t)0);
    cudaStreamWaitEvent(s_b, ev_fork, 0);

    k_zero_cnt<<<(NN + 255) / 256, 256, 0, s_b>>>();
    k_hist<<<(NE / 4 + 255) / 256, 256, 0, s_b>>>(dst);
    k_alloc<<<NB, 256, 0, s_b>>>();
    k_fill<<<(NE / 4 + 255) / 256, 256, 0, s_b>>>(src, dst);
    cudaEventRecord(ev_join, s_b);

    k_gemm1<<<NT, 256, SMEM1>>>(x, W1);

    cudaStreamWaitEvent((cudaStream_t)0, ev_join, 0);

    // agg1_lo, then gemm2_lo (side stream) concurrent with agg1_hi (main)
    k_agg1<<<SPLIT_N / 8, 256>>>(b1, 0);
    cudaEventRecord(ev_lo, (cudaStream_t)0);
    cudaStreamWaitEvent(s_b, ev_lo, 0);
    k_gemm2<<<SPLIT_T, 256, SMEM2, s_b>>>(W2, 0);
    cudaEventRecord(ev_g2lo, s_b);

    k_agg1<<<(NN - SPLIT_N + 7) / 8, 256>>>(b1, SPLIT_N);

    cudaStreamWaitEvent((cudaStream_t)0, ev_g2lo, 0);
    k_gemm2<<<NT - SPLIT_T, 256, SMEM2>>>(W2, SPLIT_T);
    k_agg2<<<(NN + 15) / 16, 256>>>(b2, out);
}

// round 16
// speedup vs baseline: 1.2675x; 1.1130x over previous
#include <cuda_runtime.h>
#include <cuda_fp16.h>

#define NN 50000
#define KD 128      // input dim of both layers (HID == IN_C == 128)
#define H1 128
#define H2 64
#define NE 800000
#define BM 128      // rows per GEMM tile
#define KC 32       // K chunk
#define NB 196      // ceil(NN/256)
#define NT ((NN + BM - 1) / BM)   // 391 row tiles

// ---------------- scratch (device globals) ---------------------------------
__device__ float g_dinv[NN];
__device__ uint4 g_h1[(size_t)NN * H1 / 8];     // x@W1, fp16 (8 halves/uint4)
__device__ float4 g_x2[(size_t)NN * H1 / 4];    // relu output (fp32) -> gemm2
__device__ uint2 g_h2[(size_t)NN * H2 / 4];     // x2@W2, fp16 (4 halves/uint2)
__device__ int g_cnt[NN];
__device__ int g_rs[NN];                        // CSR segment starts (unordered)
__device__ int g_cur[NN];                       // fill cursors
__device__ int g_csr[NE];                       // src ids grouped by dst
__device__ int g_total;                         // segment allocator

typedef unsigned long long ull;

#define FMA2(c, a, b) \
    asm("fma.rn.f32x2 %0, %1, %2, %0;" : "+l"(c) : "l"(a), "l"(b))

__device__ __forceinline__ ull dup2(float a) {
    unsigned int u = __float_as_uint(a);
    ull r;
    asm("mov.b64 %0, {%1, %1};" : "=l"(r) : "r"(u));
    return r;
}

__device__ __forceinline__ unsigned packh2(float x, float y) {
    __half2 h = __float22half2_rn(make_float2(x, y));
    return *(unsigned*)&h;
}
__device__ __forceinline__ float2 unpackh2(unsigned u) {
    return __half22float2(*(__half2*)&u);
}

__device__ __forceinline__ void cpa16(float* d, const float* s) {
    unsigned sd_ = (unsigned)__cvta_generic_to_shared(d);
    asm volatile("cp.async.cg.shared.global [%0], [%1], 16;" :: "r"(sd_), "l"(s));
}
__device__ __forceinline__ void cpa16z(float* d) {
    unsigned sd_ = (unsigned)__cvta_generic_to_shared(d);
    asm volatile("cp.async.cg.shared.global [%0], [%1], 16, 0;"
                 :: "r"(sd_), "l"((const void*)g_dinv));
}

// ---------------- CSR build -------------------------------------------------
__global__ void k_zero_cnt() {
    int i = blockIdx.x * blockDim.x + threadIdx.x;
    if (i < NN) g_cnt[i] = 0;
    if (i == 0) g_total = 0;
}

__global__ void k_hist(const int* __restrict__ dst) {
    int t = blockIdx.x * blockDim.x + threadIdx.x;
    if (t >= NE / 4) return;
    int4 d4 = ((const int4*)dst)[t];
    atomicAdd(&g_cnt[d4.x], 1);
    atomicAdd(&g_cnt[d4.y], 1);
    atomicAdd(&g_cnt[d4.z], 1);
    atomicAdd(&g_cnt[d4.w], 1);
}

__global__ void k_alloc() {
    __shared__ int sd[256];
    __shared__ int base;
    int t = threadIdx.x;
    int i = blockIdx.x * 256 + t;
    int v = (i < NN) ? g_cnt[i] : 0;
    sd[t] = v;
    __syncthreads();
    for (int off = 1; off < 256; off <<= 1) {
        int x = (t >= off) ? sd[t - off] : 0;
        __syncthreads();
        sd[t] += x;
        __syncthreads();
    }
    if (t == 255) base = atomicAdd(&g_total, sd[255]);
    __syncthreads();
    if (i < NN) {
        int rs = base + sd[t] - v;
        g_rs[i]  = rs;
        g_cur[i] = rs;
        g_dinv[i] = rsqrtf((float)(v + 1));   // deg includes self loop
    }
}

__global__ void k_fill(const int* __restrict__ src, const int* __restrict__ dst) {
    int t = blockIdx.x * blockDim.x + threadIdx.x;
    if (t >= NE / 4) return;
    int4 s4 = ((const int4*)src)[t];
    int4 d4 = ((const int4*)dst)[t];
    g_csr[atomicAdd(&g_cur[d4.x], 1)] = s4.x;
    g_csr[atomicAdd(&g_cur[d4.y], 1)] = s4.y;
    g_csr[atomicAdd(&g_cur[d4.z], 1)] = s4.z;
    g_csr[atomicAdd(&g_cur[d4.w], 1)] = s4.w;
}

// ---------------- GEMM (cp.async double-buffered, BM=128), fp16 epilogue ----
// h[i][j] = fp16( sum_k A[i][k] * W[k][j] )
template <int NC>
__device__ __forceinline__ void gemm_body(const float* __restrict__ A,
                                          const float* __restrict__ W,
                                          unsigned* __restrict__ hsu)  // half2 units
{
    constexpr int TN  = NC / 16;      // 8 / 4
    constexpr int TP  = TN / 2;       // 4 / 2
    constexpr int WS  = NC + 4;
    constexpr int AS  = KC + 4;
    constexpr int NCH = KD / KC;

    extern __shared__ float smem[];
    float* Wb0 = smem;                        // [2][KC][WS]
    float* Ab0 = smem + 2 * KC * WS;          // [2][BM][AS] row-major

    const int tid  = threadIdx.x;
    const int tx   = tid & 15, ty = tid >> 4;
    const int row0 = blockIdx.x * BM;
    const int cb   = tx * TN;

    auto issue = [&](int c) {
        float* Wb = Wb0 + (c & 1) * KC * WS;
        float* Ab = Ab0 + (c & 1) * BM * AS;
        int k0 = c * KC;
        for (int i = tid; i < KC * (NC / 4); i += 256) {
            int kk = i / (NC / 4), c4 = i % (NC / 4);
            cpa16(Wb + kk * WS + c4 * 4, W + (size_t)(k0 + kk) * NC + c4 * 4);
        }
        for (int i = tid; i < BM * (KC / 4); i += 256) {
            int r = i >> 3, c4 = i & 7;       // KC/4 == 8
            int gr = row0 + r;
            float* d = Ab + r * AS + c4 * 4;
            if (gr < NN) cpa16(d, A + (size_t)gr * KD + k0 + c4 * 4);
            else         cpa16z(d);
        }
        asm volatile("cp.async.commit_group;");
    };

    ull accp[8][TP];
#pragma unroll
    for (int i = 0; i < 8; i++)
#pragma unroll
        for (int p = 0; p < TP; p++) accp[i][p] = 0ull;

    issue(0);
    for (int c = 0; c < NCH; c++) {
        if (c + 1 < NCH) {
            issue(c + 1);
            asm volatile("cp.async.wait_group 1;");
        } else {
            asm volatile("cp.async.wait_group 0;");
        }
        __syncthreads();

        const float* arow = Ab0 + (c & 1) * BM * AS + (ty * 8) * AS;
        const float* wrow = Wb0 + (c & 1) * KC * WS + cb;
#pragma unroll 8
        for (int kk = 0; kk < KC; kk++) {
            ull ap[8];
#pragma unroll
            for (int i = 0; i < 8; i++) ap[i] = dup2(arow[i * AS + kk]);

            ull bp[4];
            float4 b0 = *(const float4*)(wrow + (size_t)kk * WS);
            bp[0] = ((const ull*)&b0)[0]; bp[1] = ((const ull*)&b0)[1];
            if (TP == 4) {
                float4 b1 = *(const float4*)(wrow + (size_t)kk * WS + 4);
                bp[2] = ((const ull*)&b1)[0]; bp[3] = ((const ull*)&b1)[1];
            }
#pragma unroll
            for (int i = 0; i < 8; i++)
#pragma unroll
                for (int p = 0; p < TP; p++)
                    FMA2(accp[i][p], ap[i], bp[p]);
        }
        __syncthreads();
    }

    // epilogue: convert to fp16, one vector store per row
#pragma unroll
    for (int i = 0; i < 8; i++) {
        int gr = row0 + ty * 8 + i;
        if (gr >= NN) continue;
        size_t baseu = ((size_t)gr * NC + cb) >> 1;   // half2 index
        unsigned u[TP];
#pragma unroll
        for (int p = 0; p < TP; p++) {
            float2 q = *(float2*)&accp[i][p];
            u[p] = packh2(q.x, q.y);
        }
        if (TP == 4) {
            uint4 st; st.x = u[0]; st.y = u[1]; st.z = u[2]; st.w = u[3];
            *(uint4*)(hsu + baseu) = st;
        } else {
            uint2 st; st.x = u[0]; st.y = u[1];
            *(uint2*)(hsu + baseu) = st;
        }
    }
}

__global__ void __launch_bounds__(256, 2) k_gemm1(const float* __restrict__ x,
                                                  const float* __restrict__ W1) {
    gemm_body<H1>(x, W1, (unsigned*)g_h1);
}
__global__ void __launch_bounds__(256, 2) k_gemm2(const float* __restrict__ W2) {
    gemm_body<H2>((const float*)g_x2, W2, (unsigned*)g_h2);
}

// ---------------- CSR pull aggregation (fp16 gathers, fp32 accum) -----------
// out = relu(dinv[d] * (dinv[d]*h[d] + sum_s dinv[s]*h[s]) + b)
__global__ void __launch_bounds__(256) k_agg1(const float* __restrict__ b1) {
    int w = blockIdx.x * 8 + (threadIdx.x >> 5);
    if (w >= NN) return;
    int lane = threadIdx.x & 31;
    const uint2* h1 = (const uint2*)g_h1;     // 4 halves per uint2

    float dd = g_dinv[w];
    float4 a;
    {
        uint2 u = h1[(size_t)w * 32 + lane];  // self loop
        float2 f0 = unpackh2(u.x), f1 = unpackh2(u.y);
        a.x = f0.x * dd; a.y = f0.y * dd; a.z = f1.x * dd; a.w = f1.y * dd;
    }

    int i   = g_rs[w];
    int end = i + g_cnt[w];
    for (; i + 4 <= end; i += 4) {
        int s0 = g_csr[i], s1 = g_csr[i + 1], s2 = g_csr[i + 2], s3 = g_csr[i + 3];
        float d0 = g_dinv[s0], d1 = g_dinv[s1], d2 = g_dinv[s2], d3 = g_dinv[s3];
        uint2 u0 = h1[(size_t)s0 * 32 + lane];
        uint2 u1 = h1[(size_t)s1 * 32 + lane];
        uint2 u2 = h1[(size_t)s2 * 32 + lane];
        uint2 u3 = h1[(size_t)s3 * 32 + lane];
        float2 p0 = unpackh2(u0.x), q0 = unpackh2(u0.y);
        float2 p1 = unpackh2(u1.x), q1 = unpackh2(u1.y);
        float2 p2 = unpackh2(u2.x), q2 = unpackh2(u2.y);
        float2 p3 = unpackh2(u3.x), q3 = unpackh2(u3.y);
        a.x += p0.x * d0 + p1.x * d1 + p2.x * d2 + p3.x * d3;
        a.y += p0.y * d0 + p1.y * d1 + p2.y * d2 + p3.y * d3;
        a.z += q0.x * d0 + q1.x * d1 + q2.x * d2 + q3.x * d3;
        a.w += q0.y * d0 + q1.y * d1 + q2.y * d2 + q3.y * d3;
    }
    for (; i < end; i++) {
        int s = g_csr[i];
        float ds = g_dinv[s];
        uint2 u = h1[(size_t)s * 32 + lane];
        float2 p = unpackh2(u.x), q = unpackh2(u.y);
        a.x += p.x * ds; a.y += p.y * ds; a.z += q.x * ds; a.w += q.y * ds;
    }
    float4 b = *(const float4*)(b1 + lane * 4);
    a.x = fmaxf(fmaf(a.x, dd, b.x), 0.f);
    a.y = fmaxf(fmaf(a.y, dd, b.y), 0.f);
    a.z = fmaxf(fmaf(a.z, dd, b.z), 0.f);
    a.w = fmaxf(fmaf(a.w, dd, b.w), 0.f);
    g_x2[(size_t)w * 32 + lane] = a;
}

__global__ void __launch_bounds__(256) k_agg2(const float* __restrict__ b2,
                                              float* __restrict__ out) {
    int g = blockIdx.x * 16 + (threadIdx.x >> 4);
    if (g >= NN) return;
    int l = threadIdx.x & 15;

    float dd = g_dinv[g];
    float4 a;
    {
        uint2 u = g_h2[(size_t)g * 16 + l];   // self loop
        float2 f0 = unpackh2(u.x), f1 = unpackh2(u.y);
        a.x = f0.x * dd; a.y = f0.y * dd; a.z = f1.x * dd; a.w = f1.y * dd;
    }

    int i   = g_rs[g];
    int end = i + g_cnt[g];
    for (; i + 4 <= end; i += 4) {
        int s0 = g_csr[i], s1 = g_csr[i + 1], s2 = g_csr[i + 2], s3 = g_csr[i + 3];
        float d0 = g_dinv[s0], d1 = g_dinv[s1], d2 = g_dinv[s2], d3 = g_dinv[s3];
        uint2 u0 = g_h2[(size_t)s0 * 16 + l];
        uint2 u1 = g_h2[(size_t)s1 * 16 + l];
        uint2 u2 = g_h2[(size_t)s2 * 16 + l];
        uint2 u3 = g_h2[(size_t)s3 * 16 + l];
        float2 p0 = unpackh2(u0.x), q0 = unpackh2(u0.y);
        float2 p1 = unpackh2(u1.x), q1 = unpackh2(u1.y);
        float2 p2 = unpackh2(u2.x), q2 = unpackh2(u2.y);
        float2 p3 = unpackh2(u3.x), q3 = unpackh2(u3.y);
        a.x += p0.x * d0 + p1.x * d1 + p2.x * d2 + p3.x * d3;
        a.y += p0.y * d0 + p1.y * d1 + p2.y * d2 + p3.y * d3;
        a.z += q0.x * d0 + q1.x * d1 + q2.x * d2 + q3.x * d3;
        a.w += q0.y * d0 + q1.y * d1 + q2.y * d2 + q3.y * d3;
    }
    for (; i < end; i++) {
        int s = g_csr[i];
        float ds = g_dinv[s];
        uint2 u = g_h2[(size_t)s * 16 + l];
        float2 p = unpackh2(u.x), q = unpackh2(u.y);
        a.x += p.x * ds; a.y += p.y * ds; a.z += q.x * ds; a.w += q.y * ds;
    }
    float4 b = *(const float4*)(b2 + l * 4);
    a.x = fmaf(a.x, dd, b.x);
    a.y = fmaf(a.y, dd, b.y);
    a.z = fmaf(a.z, dd, b.z);
    a.w = fmaf(a.w, dd, b.w);
    *(float4*)(out + (size_t)g * H2 + l * 4) = a;
}

// ---------------- launch ----------------------------------------------------
extern "C" void kernel_launch(void* const* d_in, const int* in_sizes, int n_in,
                              void* d_out, int out_size)
{
    const float* x  = (const float*)d_in[0];
    const int*   ei = (const int*)d_in[1];    // int32 (JAX default, x64 disabled)
    const float* W1 = (const float*)d_in[2];
    const float* b1 = (const float*)d_in[3];
    const float* W2 = (const float*)d_in[4];
    const float* b2 = (const float*)d_in[5];
    float* out = (float*)d_out;

    const int* src = ei;        // edge_index[0]
    const int* dst = ei + NE;   // edge_index[1]

    const int SMEM1 = (2 * KC * (H1 + 4) + 2 * BM * (KC + 4)) * (int)sizeof(float);
    const int SMEM2 = (2 * KC * (H2 + 4) + 2 * BM * (KC + 4)) * (int)sizeof(float);
    cudaFuncSetAttribute(k_gemm1, cudaFuncAttributeMaxDynamicSharedMemorySize, SMEM1);
    cudaFuncSetAttribute(k_gemm2, cudaFuncAttributeMaxDynamicSharedMemorySize, SMEM2);

    static cudaStream_t s_b = nullptr;
    static cudaEvent_t  ev_fork = nullptr, ev_join = nullptr;
    if (s_b == nullptr) {
        cudaStreamCreateWithFlags(&s_b, cudaStreamNonBlocking);
        cudaEventCreateWithFlags(&ev_fork, cudaEventDisableTiming);
        cudaEventCreateWithFlags(&ev_join, cudaEventDisableTiming);
    }

    // fork: CSR build concurrent with gemm1 (gemm does not read g_dinv)
    cudaEventRecord(ev_fork, (cudaStream_t)0);
    cudaStreamWaitEvent(s_b, ev_fork, 0);

    k_zero_cnt<<<(NN + 255) / 256, 256, 0, s_b>>>();
    k_hist<<<(NE / 4 + 255) / 256, 256, 0, s_b>>>(dst);
    k_alloc<<<NB, 256, 0, s_b>>>();
    k_fill<<<(NE / 4 + 255) / 256, 256, 0, s_b>>>(src, dst);
    cudaEventRecord(ev_join, s_b);

    k_gemm1<<<NT, 256, SMEM1>>>(x, W1);

    cudaStreamWaitEvent((cudaStream_t)0, ev_join, 0);

    k_agg1<<<(NN + 7) / 8, 256>>>(b1);
    k_gemm2<<<NT, 256, SMEM2>>>(W2);
    k_agg2<<<(NN + 15) / 16, 256>>>(b2, out);
}